// round 9
// baseline (speedup 1.0000x reference)
#include <cuda_runtime.h>
#include <cstdint>

// ============================================================================
// Experts — two-stage GEMM via mma.sync tf32 (sm_103 base target)
// Round 8: byte-identical resubmit of round 7 (infra failed twice; kernel
// never ran). Warp-rotated k-substep order (ks = (s+wid)&3) to de-correlate
// LDS-burst and MMA-burst phases across warps after each __syncthreads.
//   x  : [4,2048,512] f32  -> flat [8192,512]
//   w1 : [16,512,512] f32   == B for GEMM1 (row.col)
//   w2 : [16,512,128] f32   == B for GEMM2
//   out: [4,2048,128,16] f32, out[(tok*128 + d)*16 + e]
// ============================================================================

#define DEVINL __device__ __forceinline__

constexpr int NE   = 16;
constexpr int DIM  = 512;
constexpr int HID  = 512;
constexpr int DOUT = 128;
constexpr int TOK  = 8192;

constexpr int M   = 128;            // token tile
constexpr int KC  = 32;             // k-chunk
constexpr int NKC = DIM / KC;       // 16

// tf32-pre-rounded inputs + hidden scratch
__device__ float g_xr [TOK * DIM];
__device__ float g_w1r[NE * DIM * HID];
__device__ float g_w2r[NE * HID * DOUT];
__device__ float g_h  [(size_t)NE * TOK * HID];   // 256 MB

// SMEM layout in floats (identical for both GEMM kernels)
constexpr int LDX  = 36;            // A tile row stride (bank = 4tq+tr, free)
constexpr int LDB  = 136;           // B tile row stride (bank = 8tr+tq, free)
constexpr int AS0  = 0;
constexpr int AS1  = AS0 + M * LDX;          // 4608
constexpr int BS0  = AS1 + M * LDX;          // 9216
constexpr int BS1  = BS0 + KC * LDB;         // 13568
constexpr int SMEM_FLOATS = BS1 + KC * LDB;  // 17920
constexpr int SMEM_BYTES  = SMEM_FLOATS * 4; // 71680

// ---------------------------------------------------------------------------
DEVINL uint32_t smem_u32(const void* p) {
    uint32_t a;
    asm("{ .reg .u64 t; cvta.to.shared.u64 t, %1; cvt.u32.u64 %0, t; }"
        : "=r"(a) : "l"(p));
    return a;
}

DEVINL void cp16(uint32_t dst, const float* src) {
    asm volatile("cp.async.cg.shared.global [%0], [%1], 16;"
                 :: "r"(dst), "l"(src) : "memory");
}
DEVINL void cp_commit() { asm volatile("cp.async.commit_group;" ::: "memory"); }
template <int N>
DEVINL void cp_wait() { asm volatile("cp.async.wait_group %0;" :: "n"(N) : "memory"); }

DEVINL uint32_t f2tf(float f) {
    uint32_t r;
    asm("cvt.rna.tf32.f32 %0, %1;" : "=r"(r) : "f"(f));
    return r;
}

DEVINL void mma8(float* c, const uint32_t* a, const uint32_t* b) {
    asm volatile(
        "mma.sync.aligned.m16n8k8.row.col.f32.tf32.tf32.f32 "
        "{%0,%1,%2,%3}, {%4,%5,%6,%7}, {%8,%9}, {%0,%1,%2,%3};"
        : "+f"(c[0]), "+f"(c[1]), "+f"(c[2]), "+f"(c[3])
        : "r"(a[0]), "r"(a[1]), "r"(a[2]), "r"(a[3]), "r"(b[0]), "r"(b[1]));
}

DEVINL float gelu_exact(float v) {
    return 0.5f * v * (1.0f + erff(v * 0.70710678118654752f));
}

// ---------------------------------------------------------------------------
// prep: round fp32 -> tf32 bit pattern (float4)
// ---------------------------------------------------------------------------
__global__ void round_tf32_kernel(const float* __restrict__ src,
                                  float* __restrict__ dst, int n4) {
    int i = blockIdx.x * blockDim.x + threadIdx.x;
    if (i < n4) {
        float4 v = reinterpret_cast<const float4*>(src)[i];
        v.x = __uint_as_float(f2tf(v.x));
        v.y = __uint_as_float(f2tf(v.y));
        v.z = __uint_as_float(f2tf(v.z));
        v.w = __uint_as_float(f2tf(v.w));
        reinterpret_cast<float4*>(dst)[i] = v;
    }
}

// ---------------------------------------------------------------------------
// shared copy helpers: A tile is [128 tok-rows x 32 k], B tile is [32 k x 128 n]
// ---------------------------------------------------------------------------
DEVINL void copy_a_chunk(uint32_t sbase, int tid, const float* __restrict__ src,
                         int ld) {
#pragma unroll
    for (int i = 0; i < 4; i++) {
        int idx = tid + i * 256;              // 0..1023
        int row = idx >> 3;                   // 0..127
        int v   = idx & 7;                    // float4 col
        cp16(sbase + (uint32_t)(row * LDX + v * 4) * 4,
             src + (size_t)row * ld + v * 4);
    }
}
DEVINL void copy_b_chunk(uint32_t sbase, int tid, const float* __restrict__ src,
                         int ld) {
#pragma unroll
    for (int i = 0; i < 4; i++) {
        int idx = tid + i * 256;
        int row = idx >> 5;                   // 0..31 (k)
        int v   = idx & 31;                   // float4 col (n/4)
        cp16(sbase + (uint32_t)(row * LDB + v * 4) * 4,
             src + (size_t)row * ld + v * 4);
    }
}

// ---------------------------------------------------------------------------
// generic 128x128xK512 tf32 mainloop body (A row-major, B row.col)
// c[2][8][4] accumulators; 8 warps 4x2, warp tile 32x64.
// k8-substeps rotated per warp to overlap LDS and MMA phases across warps.
// ---------------------------------------------------------------------------
DEVINL void gemm_mainloop(const float* __restrict__ a_g, int lda,
                          const float* __restrict__ b_g, int ldb,
                          float* smf, uint32_t sb, int tid, int wid,
                          int wr, int wc, int tq, int tr,
                          float c[2][8][4]) {
    copy_a_chunk(sb + AS0 * 4, tid, a_g, lda);
    copy_b_chunk(sb + BS0 * 4, tid, b_g, ldb);
    cp_commit();

    for (int kc = 0; kc < NKC; kc++) {
        if (kc + 1 < NKC) {
            uint32_t ab = sb + (((kc + 1) & 1) ? AS1 : AS0) * 4;
            uint32_t bb = sb + (((kc + 1) & 1) ? BS1 : BS0) * 4;
            copy_a_chunk(ab, tid, a_g + (kc + 1) * KC, lda);
            copy_b_chunk(bb, tid, b_g + (size_t)(kc + 1) * KC * ldb, ldb);
            cp_commit();
            cp_wait<1>();
        } else {
            cp_wait<0>();
        }
        __syncthreads();

        const float* Ab = smf + ((kc & 1) ? AS1 : AS0);
        const float* Bb = smf + ((kc & 1) ? BS1 : BS0);
#pragma unroll
        for (int s = 0; s < 4; s++) {
            const int ks = (s + wid) & 3;     // per-warp rotated substep
            const int k0 = ks * 8;
            uint32_t a[2][4], b[8][2];
#pragma unroll
            for (int mi = 0; mi < 2; mi++) {
                const int m0 = wr * 32 + mi * 16;
                a[mi][0] = __float_as_uint(Ab[(m0 + tq) * LDX + k0 + tr]);
                a[mi][1] = __float_as_uint(Ab[(m0 + tq + 8) * LDX + k0 + tr]);
                a[mi][2] = __float_as_uint(Ab[(m0 + tq) * LDX + k0 + tr + 4]);
                a[mi][3] = __float_as_uint(Ab[(m0 + tq + 8) * LDX + k0 + tr + 4]);
            }
#pragma unroll
            for (int ni = 0; ni < 8; ni++) {
                const int n0 = wc * 64 + ni * 8;
                b[ni][0] = __float_as_uint(Bb[(k0 + tr) * LDB + n0 + tq]);
                b[ni][1] = __float_as_uint(Bb[(k0 + tr + 4) * LDB + n0 + tq]);
            }
#pragma unroll
            for (int mi = 0; mi < 2; mi++)
#pragma unroll
                for (int ni = 0; ni < 8; ni++)
                    mma8(c[mi][ni], a[mi], b[ni]);
        }
        __syncthreads();
    }
}

// ---------------------------------------------------------------------------
// Kernel A: H[e][tok][h] = tf32(gelu(X @ W1[e]))   grid (64 n/e combos, 64 tiles)
// ---------------------------------------------------------------------------
__global__ void __launch_bounds__(256, 2)
gemm1_gelu_kernel() {
    extern __shared__ __align__(16) float smf[];
    const uint32_t sb = smem_u32(smf);

    const int tid = threadIdx.x;
    const int wid = tid >> 5, lid = tid & 31;
    const int wr = wid >> 1, wc = wid & 1;
    const int tq = lid >> 2, tr = lid & 3;

    const int e    = blockIdx.x & (NE - 1);
    const int nt   = blockIdx.x >> 4;        // 0..3 hidden 128-col tile
    const int tile = blockIdx.y;

    const float* a_g = g_xr  + (size_t)tile * M * DIM;
    const float* b_g = g_w1r + (size_t)e * DIM * HID + nt * 128;

    float c[2][8][4];
#pragma unroll
    for (int mi = 0; mi < 2; mi++)
#pragma unroll
        for (int ni = 0; ni < 8; ni++)
#pragma unroll
            for (int j = 0; j < 4; j++) c[mi][ni][j] = 0.f;

    gemm_mainloop(a_g, DIM, b_g, HID, smf, sb, tid, wid, wr, wc, tq, tr, c);

    // epilogue: gelu + tf32-round + store to H (h contiguous)
    float* hg = g_h + ((size_t)e * TOK + (size_t)tile * M) * HID + nt * 128;
#pragma unroll
    for (int mi = 0; mi < 2; mi++) {
        const int m0 = wr * 32 + mi * 16;
#pragma unroll
        for (int ni = 0; ni < 8; ni++) {
            const int n0 = wc * 64 + ni * 8 + 2 * tr;
            float2 v0, v1;
            v0.x = __uint_as_float(f2tf(gelu_exact(c[mi][ni][0])));
            v0.y = __uint_as_float(f2tf(gelu_exact(c[mi][ni][1])));
            v1.x = __uint_as_float(f2tf(gelu_exact(c[mi][ni][2])));
            v1.y = __uint_as_float(f2tf(gelu_exact(c[mi][ni][3])));
            *reinterpret_cast<float2*>(hg + (size_t)(m0 + tq) * HID + n0)     = v0;
            *reinterpret_cast<float2*>(hg + (size_t)(m0 + tq + 8) * HID + n0) = v1;
        }
    }
}

// ---------------------------------------------------------------------------
// Kernel B: out = H[e] @ W2[e]   grid (16 experts, 64 tiles)
// ---------------------------------------------------------------------------
__global__ void __launch_bounds__(256, 2)
gemm2_kernel(float* __restrict__ out) {
    extern __shared__ __align__(16) float smf[];
    const uint32_t sb = smem_u32(smf);

    const int tid = threadIdx.x;
    const int wid = tid >> 5, lid = tid & 31;
    const int wr = wid >> 1, wc = wid & 1;
    const int tq = lid >> 2, tr = lid & 3;

    const int e    = blockIdx.x;
    const int tile = blockIdx.y;

    const float* a_g = g_h   + ((size_t)e * TOK + (size_t)tile * M) * HID;
    const float* b_g = g_w2r + (size_t)e * HID * DOUT;

    float c[2][8][4];
#pragma unroll
    for (int mi = 0; mi < 2; mi++)
#pragma unroll
        for (int ni = 0; ni < 8; ni++)
#pragma unroll
            for (int j = 0; j < 4; j++) c[mi][ni][j] = 0.f;

    gemm_mainloop(a_g, HID, b_g, DOUT, smf, sb, tid, wid, wr, wc, tq, tr, c);

    // epilogue: scatter to out[(tok*128 + d)*16 + e]
#pragma unroll
    for (int mi = 0; mi < 2; mi++) {
        const size_t tok0 = (size_t)tile * M + wr * 32 + mi * 16 + tq;
#pragma unroll
        for (int ni = 0; ni < 8; ni++) {
            const int d0 = wc * 64 + ni * 8 + 2 * tr;
            out[(tok0 * DOUT + d0) * NE + e]           = c[mi][ni][0];
            out[(tok0 * DOUT + d0 + 1) * NE + e]       = c[mi][ni][1];
            out[((tok0 + 8) * DOUT + d0) * NE + e]     = c[mi][ni][2];
            out[((tok0 + 8) * DOUT + d0 + 1) * NE + e] = c[mi][ni][3];
        }
    }
}

// ---------------------------------------------------------------------------
extern "C" void kernel_launch(void* const* d_in, const int* in_sizes, int n_in,
                              void* d_out, int out_size) {
    const float* x  = (const float*)d_in[0];
    const float* w1 = (const float*)d_in[1];
    const float* w2 = (const float*)d_in[2];
    float* out      = (float*)d_out;

    float* xr;  cudaGetSymbolAddress((void**)&xr,  g_xr);
    float* w1r; cudaGetSymbolAddress((void**)&w1r, g_w1r);
    float* w2r; cudaGetSymbolAddress((void**)&w2r, g_w2r);

    constexpr int NX  = TOK * DIM / 4;
    constexpr int NW1 = NE * DIM * HID / 4;
    constexpr int NW2 = NE * HID * DOUT / 4;
    round_tf32_kernel<<<(NX  + 255) / 256, 256>>>(x,  xr,  NX);
    round_tf32_kernel<<<(NW1 + 255) / 256, 256>>>(w1, w1r, NW1);
    round_tf32_kernel<<<(NW2 + 255) / 256, 256>>>(w2, w2r, NW2);

    cudaFuncSetAttribute(gemm1_gelu_kernel,
                         cudaFuncAttributeMaxDynamicSharedMemorySize, SMEM_BYTES);
    cudaFuncSetAttribute(gemm2_kernel,
                         cudaFuncAttributeMaxDynamicSharedMemorySize, SMEM_BYTES);

    gemm1_gelu_kernel<<<dim3(NE * (HID / 128), TOK / M), 256, SMEM_BYTES>>>();
    gemm2_kernel<<<dim3(NE, TOK / M), 256, SMEM_BYTES>>>(out);
}

// round 10
// speedup vs baseline: 1.0749x; 1.0749x over previous
#include <cuda_runtime.h>
#include <cstdint>

// ============================================================================
// Experts — two-stage GEMM via mma.sync tf32 (sm_103 base target)
// Round 9: fragment-packed operands. X and W are pre-packed in prep kernels
// into exact mma-fragment order so the mainloop uses LDS.128 (A) / LDS.64 (B)
// instead of 24 scalar LDS per k8-step. gemm1: 96->40 LDS per warp-kc.
//   x  : [4,2048,512] f32 ; w1 : [16,512,512] ; w2 : [16,512,128]
//   out: [4,2048,128,16] f32, out[(tok*128 + d)*16 + e]
// ============================================================================

#define DEVINL __device__ __forceinline__

constexpr int NE   = 16;
constexpr int DIM  = 512;
constexpr int HID  = 512;
constexpr int DOUT = 128;
constexpr int TOK  = 8192;

constexpr int M     = 128;
constexpr int KC    = 32;
constexpr int NKC   = DIM / KC;     // 16
constexpr int CHUNK = 4096;         // floats per packed 16KB tile chunk

// packed/staged buffers
__device__ float g_xa [TOK * DIM];            // packed A chunks for gemm1
__device__ float g_w1p[NE * DIM * HID];       // packed B chunks for gemm1
__device__ float g_w2p[NE * HID * DOUT];      // packed B chunks for gemm2
__device__ float g_h  [(size_t)NE * TOK * HID]; // H row-major (gemm2 A)

// gemm1 SMEM (floats): linear packed tiles, double buffered
constexpr int G1_AS0 = 0;
constexpr int G1_AS1 = CHUNK;
constexpr int G1_BS0 = 2 * CHUNK;
constexpr int G1_BS1 = 3 * CHUNK;
constexpr int G1_BYTES = 4 * CHUNK * 4;       // 65536

// gemm2 SMEM: A row-major padded, B packed
constexpr int LDX    = 36;                    // A row stride (bank = 4tq+tr)
constexpr int G2_AS0 = 0;
constexpr int G2_AS1 = M * LDX;               // 4608
constexpr int G2_BS0 = 2 * M * LDX;           // 9216
constexpr int G2_BS1 = G2_BS0 + CHUNK;        // 13312
constexpr int G2_BYTES = (G2_BS1 + CHUNK) * 4; // 69632

// ---------------------------------------------------------------------------
DEVINL uint32_t smem_u32(const void* p) {
    uint32_t a;
    asm("{ .reg .u64 t; cvta.to.shared.u64 t, %1; cvt.u32.u64 %0, t; }"
        : "=r"(a) : "l"(p));
    return a;
}

DEVINL void cp16(uint32_t dst, const float* src) {
    asm volatile("cp.async.cg.shared.global [%0], [%1], 16;"
                 :: "r"(dst), "l"(src) : "memory");
}
DEVINL void cp_commit() { asm volatile("cp.async.commit_group;" ::: "memory"); }
template <int N>
DEVINL void cp_wait() { asm volatile("cp.async.wait_group %0;" :: "n"(N) : "memory"); }

DEVINL uint32_t f2tf(float f) {
    uint32_t r;
    asm("cvt.rna.tf32.f32 %0, %1;" : "=r"(r) : "f"(f));
    return r;
}
DEVINL float f2tf_f(float f) { return __uint_as_float(f2tf(f)); }

DEVINL void mma8(float* c, uint4 a, uint2 b) {
    asm volatile(
        "mma.sync.aligned.m16n8k8.row.col.f32.tf32.tf32.f32 "
        "{%0,%1,%2,%3}, {%4,%5,%6,%7}, {%8,%9}, {%0,%1,%2,%3};"
        : "+f"(c[0]), "+f"(c[1]), "+f"(c[2]), "+f"(c[3])
        : "r"(a.x), "r"(a.y), "r"(a.z), "r"(a.w), "r"(b.x), "r"(b.y));
}

DEVINL float gelu_exact(float v) {
    return 0.5f * v * (1.0f + erff(v * 0.70710678118654752f));
}

// ---------------------------------------------------------------------------
// Packing prep kernels.
// A-chunk layout (per (tile,kc), 4096 floats): ((mblk*4 + ks)*32 + lane)*4 + j
//   lane = tq*4+tr ; j: 0=(tq,tr) 1=(tq+8,tr) 2=(tq,tr+4) 3=(tq+8,tr+4)
// B-chunk layout (per chunk, 4096 floats): ((ks*16 + nblk)*32 + lane)*2 + j
//   j: 0=(k0+tr, n0+tq) 1=(k0+tr+4, n0+tq)
// ---------------------------------------------------------------------------
__global__ void pack_x_kernel(const float* __restrict__ x) {
    int i = blockIdx.x * blockDim.x + threadIdx.x;      // float4 index
    if (i >= TOK * DIM / 4) return;
    int fi    = i * 4;
    int chunk = fi / CHUNK;
    int tile  = chunk / NKC, kc = chunk % NKC;
    int inner = fi % CHUNK;
    int mblk  = inner / 512;
    int ks    = (inner % 512) / 128;
    int lane  = (inner % 128) / 4;
    int tq = lane >> 2, tr = lane & 3;
    int mb = tile * 128 + mblk * 16 + tq;
    int kb = kc * 32 + ks * 8 + tr;
    float4 v;
    v.x = f2tf_f(x[(size_t)mb * DIM + kb]);
    v.y = f2tf_f(x[(size_t)(mb + 8) * DIM + kb]);
    v.z = f2tf_f(x[(size_t)mb * DIM + kb + 4]);
    v.w = f2tf_f(x[(size_t)(mb + 8) * DIM + kb + 4]);
    reinterpret_cast<float4*>(g_xa)[i] = v;
}

// w1 chunks ordered [e][nt][kc]; w2 chunks ordered [e][kc]
__global__ void pack_w1_kernel(const float* __restrict__ w1) {
    int i = blockIdx.x * blockDim.x + threadIdx.x;      // float4 index
    if (i >= NE * DIM * HID / 4) return;
    int fi    = i * 4;
    int chunk = fi / CHUNK;
    int e  = chunk >> 6;
    int nt = (chunk >> 4) & 3;
    int kc = chunk & 15;
    int inner = fi % CHUNK;
    int ks    = inner / 1024;
    int nblk  = (inner % 1024) / 64;
    int lane0 = (inner % 64) / 2;               // fi%4==0 -> even pair start
    int lane1 = lane0 + 1;
    int tq0 = lane0 >> 2, tr0 = lane0 & 3;
    int tq1 = lane1 >> 2, tr1 = lane1 & 3;
    int kb = kc * 32 + ks * 8;
    int nb = nt * 128 + nblk * 8;
    const float* we = w1 + (size_t)e * DIM * HID;
    float4 v;
    v.x = f2tf_f(we[(size_t)(kb + tr0) * HID + nb + tq0]);
    v.y = f2tf_f(we[(size_t)(kb + tr0 + 4) * HID + nb + tq0]);
    v.z = f2tf_f(we[(size_t)(kb + tr1) * HID + nb + tq1]);
    v.w = f2tf_f(we[(size_t)(kb + tr1 + 4) * HID + nb + tq1]);
    reinterpret_cast<float4*>(g_w1p)[i] = v;
}

__global__ void pack_w2_kernel(const float* __restrict__ w2) {
    int i = blockIdx.x * blockDim.x + threadIdx.x;      // float4 index
    if (i >= NE * HID * DOUT / 4) return;
    int fi    = i * 4;
    int chunk = fi / CHUNK;
    int e  = chunk >> 4;
    int kc = chunk & 15;
    int inner = fi % CHUNK;
    int ks    = inner / 1024;
    int nblk  = (inner % 1024) / 64;
    int lane0 = (inner % 64) / 2;
    int lane1 = lane0 + 1;
    int tq0 = lane0 >> 2, tr0 = lane0 & 3;
    int tq1 = lane1 >> 2, tr1 = lane1 & 3;
    int kb = kc * 32 + ks * 8;
    int nb = nblk * 8;
    const float* we = w2 + (size_t)e * HID * DOUT;
    float4 v;
    v.x = f2tf_f(we[(size_t)(kb + tr0) * DOUT + nb + tq0]);
    v.y = f2tf_f(we[(size_t)(kb + tr0 + 4) * DOUT + nb + tq0]);
    v.z = f2tf_f(we[(size_t)(kb + tr1) * DOUT + nb + tq1]);
    v.w = f2tf_f(we[(size_t)(kb + tr1 + 4) * DOUT + nb + tq1]);
    reinterpret_cast<float4*>(g_w2p)[i] = v;
}

// ---------------------------------------------------------------------------
// copy helpers
// ---------------------------------------------------------------------------
DEVINL void copy_packed(uint32_t sbase, int tid, const float* __restrict__ src) {
#pragma unroll
    for (int i = 0; i < 4; i++) {
        int idx = tid + i * 256;
        cp16(sbase + (uint32_t)idx * 16, src + (size_t)idx * 4);
    }
}
DEVINL void copy_a_rowmajor(uint32_t sbase, int tid, const float* __restrict__ src,
                            int ld) {
#pragma unroll
    for (int i = 0; i < 4; i++) {
        int idx = tid + i * 256;
        int row = idx >> 3;
        int v   = idx & 7;
        cp16(sbase + (uint32_t)(row * LDX + v * 4) * 4,
             src + (size_t)row * ld + v * 4);
    }
}

// ---------------------------------------------------------------------------
// Kernel A: H = gelu(X @ W1)  — fully packed operands.
// grid (NE*4, 64 tiles), 256 threads, warp grid 4x2 (tile 32x64)
// ---------------------------------------------------------------------------
__global__ void __launch_bounds__(256, 2)
gemm1_gelu_kernel() {
    extern __shared__ __align__(16) float smf[];
    const uint32_t sb = smem_u32(smf);

    const int tid = threadIdx.x;
    const int wid = tid >> 5, lid = tid & 31;
    const int wr = wid >> 1, wc = wid & 1;
    const int tq = lid >> 2, tr = lid & 3;

    const int e    = blockIdx.x & (NE - 1);
    const int nt   = blockIdx.x >> 4;
    const int tile = blockIdx.y;

    const float* a_g = g_xa  + (size_t)tile * NKC * CHUNK;
    const float* b_g = g_w1p + (size_t)(e * 4 + nt) * NKC * CHUNK;

    float c[2][8][4];
#pragma unroll
    for (int mi = 0; mi < 2; mi++)
#pragma unroll
        for (int ni = 0; ni < 8; ni++)
#pragma unroll
            for (int j = 0; j < 4; j++) c[mi][ni][j] = 0.f;

    copy_packed(sb + G1_AS0 * 4, tid, a_g);
    copy_packed(sb + G1_BS0 * 4, tid, b_g);
    cp_commit();

    for (int kc = 0; kc < NKC; kc++) {
        if (kc + 1 < NKC) {
            copy_packed(sb + (((kc + 1) & 1) ? G1_AS1 : G1_AS0) * 4, tid,
                        a_g + (size_t)(kc + 1) * CHUNK);
            copy_packed(sb + (((kc + 1) & 1) ? G1_BS1 : G1_BS0) * 4, tid,
                        b_g + (size_t)(kc + 1) * CHUNK);
            cp_commit();
            cp_wait<1>();
        } else {
            cp_wait<0>();
        }
        __syncthreads();

        const float* Af = smf + ((kc & 1) ? G1_AS1 : G1_AS0);
        const float* Bf = smf + ((kc & 1) ? G1_BS1 : G1_BS0);
#pragma unroll
        for (int ks = 0; ks < 4; ks++) {
            uint4 a[2];
            uint2 b[8];
#pragma unroll
            for (int mi = 0; mi < 2; mi++)
                a[mi] = *reinterpret_cast<const uint4*>(
                    Af + ((wr * 2 + mi) * 4 + ks) * 128 + lid * 4);
#pragma unroll
            for (int ni = 0; ni < 8; ni++)
                b[ni] = *reinterpret_cast<const uint2*>(
                    Bf + (ks * 16 + wc * 8 + ni) * 64 + lid * 2);
#pragma unroll
            for (int mi = 0; mi < 2; mi++)
#pragma unroll
                for (int ni = 0; ni < 8; ni++)
                    mma8(c[mi][ni], a[mi], b[ni]);
        }
        __syncthreads();
    }

    // epilogue: gelu + tf32-round + store to H row-major (h contiguous)
    float* hg = g_h + ((size_t)e * TOK + (size_t)tile * M) * HID + nt * 128;
#pragma unroll
    for (int mi = 0; mi < 2; mi++) {
        const int m0 = wr * 32 + mi * 16;
#pragma unroll
        for (int ni = 0; ni < 8; ni++) {
            const int n0 = wc * 64 + ni * 8 + 2 * tr;
            float2 v0, v1;
            v0.x = f2tf_f(gelu_exact(c[mi][ni][0]));
            v0.y = f2tf_f(gelu_exact(c[mi][ni][1]));
            v1.x = f2tf_f(gelu_exact(c[mi][ni][2]));
            v1.y = f2tf_f(gelu_exact(c[mi][ni][3]));
            *reinterpret_cast<float2*>(hg + (size_t)(m0 + tq) * HID + n0)     = v0;
            *reinterpret_cast<float2*>(hg + (size_t)(m0 + tq + 8) * HID + n0) = v1;
        }
    }
}

// ---------------------------------------------------------------------------
// Kernel B: out = H @ W2 — A row-major (LDS.32), B packed (LDS.64).
// grid (16, 64), 256 threads, warp grid 4x2
// ---------------------------------------------------------------------------
__global__ void __launch_bounds__(256, 2)
gemm2_kernel(float* __restrict__ out) {
    extern __shared__ __align__(16) float smf[];
    const uint32_t sb = smem_u32(smf);

    const int tid = threadIdx.x;
    const int wid = tid >> 5, lid = tid & 31;
    const int wr = wid >> 1, wc = wid & 1;
    const int tq = lid >> 2, tr = lid & 3;

    const int e    = blockIdx.x;
    const int tile = blockIdx.y;

    const float* a_g = g_h   + ((size_t)e * TOK + (size_t)tile * M) * HID;
    const float* b_g = g_w2p + (size_t)e * NKC * CHUNK;

    float c[2][8][4];
#pragma unroll
    for (int mi = 0; mi < 2; mi++)
#pragma unroll
        for (int ni = 0; ni < 8; ni++)
#pragma unroll
            for (int j = 0; j < 4; j++) c[mi][ni][j] = 0.f;

    copy_a_rowmajor(sb + G2_AS0 * 4, tid, a_g, HID);
    copy_packed(sb + G2_BS0 * 4, tid, b_g);
    cp_commit();

    for (int kc = 0; kc < NKC; kc++) {
        if (kc + 1 < NKC) {
            copy_a_rowmajor(sb + (((kc + 1) & 1) ? G2_AS1 : G2_AS0) * 4, tid,
                            a_g + (kc + 1) * KC, HID);
            copy_packed(sb + (((kc + 1) & 1) ? G2_BS1 : G2_BS0) * 4, tid,
                        b_g + (size_t)(kc + 1) * CHUNK);
            cp_commit();
            cp_wait<1>();
        } else {
            cp_wait<0>();
        }
        __syncthreads();

        const float* Ab = smf + ((kc & 1) ? G2_AS1 : G2_AS0);
        const float* Bf = smf + ((kc & 1) ? G2_BS1 : G2_BS0);
#pragma unroll
        for (int ks = 0; ks < 4; ks++) {
            const int k0 = ks * 8;
            uint4 a[2];
            uint2 b[8];
#pragma unroll
            for (int mi = 0; mi < 2; mi++) {
                const int m0 = wr * 32 + mi * 16;
                a[mi].x = __float_as_uint(Ab[(m0 + tq) * LDX + k0 + tr]);
                a[mi].y = __float_as_uint(Ab[(m0 + tq + 8) * LDX + k0 + tr]);
                a[mi].z = __float_as_uint(Ab[(m0 + tq) * LDX + k0 + tr + 4]);
                a[mi].w = __float_as_uint(Ab[(m0 + tq + 8) * LDX + k0 + tr + 4]);
            }
#pragma unroll
            for (int ni = 0; ni < 8; ni++)
                b[ni] = *reinterpret_cast<const uint2*>(
                    Bf + (ks * 16 + wc * 8 + ni) * 64 + lid * 2);
#pragma unroll
            for (int mi = 0; mi < 2; mi++)
#pragma unroll
                for (int ni = 0; ni < 8; ni++)
                    mma8(c[mi][ni], a[mi], b[ni]);
        }
        __syncthreads();
    }

    // epilogue: scatter to out[(tok*128 + d)*16 + e]
#pragma unroll
    for (int mi = 0; mi < 2; mi++) {
        const size_t tok0 = (size_t)tile * M + wr * 32 + mi * 16 + tq;
#pragma unroll
        for (int ni = 0; ni < 8; ni++) {
            const int d0 = wc * 64 + ni * 8 + 2 * tr;
            out[(tok0 * DOUT + d0) * NE + e]           = c[mi][ni][0];
            out[(tok0 * DOUT + d0 + 1) * NE + e]       = c[mi][ni][1];
            out[((tok0 + 8) * DOUT + d0) * NE + e]     = c[mi][ni][2];
            out[((tok0 + 8) * DOUT + d0 + 1) * NE + e] = c[mi][ni][3];
        }
    }
}

// ---------------------------------------------------------------------------
extern "C" void kernel_launch(void* const* d_in, const int* in_sizes, int n_in,
                              void* d_out, int out_size) {
    const float* x  = (const float*)d_in[0];
    const float* w1 = (const float*)d_in[1];
    const float* w2 = (const float*)d_in[2];
    float* out      = (float*)d_out;

    constexpr int NX  = TOK * DIM / 4;
    constexpr int NW1 = NE * DIM * HID / 4;
    constexpr int NW2 = NE * HID * DOUT / 4;
    pack_x_kernel <<<(NX  + 255) / 256, 256>>>(x);
    pack_w1_kernel<<<(NW1 + 255) / 256, 256>>>(w1);
    pack_w2_kernel<<<(NW2 + 255) / 256, 256>>>(w2);

    cudaFuncSetAttribute(gemm1_gelu_kernel,
                         cudaFuncAttributeMaxDynamicSharedMemorySize, G1_BYTES);
    cudaFuncSetAttribute(gemm2_kernel,
                         cudaFuncAttributeMaxDynamicSharedMemorySize, G2_BYTES);

    gemm1_gelu_kernel<<<dim3(NE * (HID / 128), TOK / M), 256, G1_BYTES>>>();
    gemm2_kernel<<<dim3(NE, TOK / M), 256, G2_BYTES>>>(out);
}

// round 11
// speedup vs baseline: 1.5813x; 1.4711x over previous
#include <cuda_runtime.h>
#include <cuda_fp16.h>
#include <cstdint>

// ============================================================================
// Experts — two-stage GEMM via mma.sync fp16 m16n8k16 (sm_103 base target)
// Round 10: tf32 -> fp16. Same 10-bit mantissa as tf32 (rel_err preserved),
// 2x tensor rate + half the MMA instructions + half the SMEM/DRAM bytes.
//   x  : [4,2048,512] f32 ; w1 : [16,512,512] ; w2 : [16,512,128]
//   out: [4,2048,128,16] f32, out[(tok*128 + d)*16 + e]
// ============================================================================

#define DEVINL __device__ __forceinline__

constexpr int NE   = 16;
constexpr int DIM  = 512;
constexpr int HID  = 512;
constexpr int DOUT = 128;
constexpr int TOK  = 8192;

constexpr int M   = 128;
constexpr int KC  = 32;             // k elements per chunk
constexpr int NKC = DIM / KC;       // 16
constexpr int CH  = 4096;           // halves per packed chunk (8KB)

// packed half buffers
__device__ __half g_xa [TOK * DIM];             // gemm1 A, fragment-packed
__device__ __half g_w1p[NE * DIM * HID];        // gemm1 B, fragment-packed
__device__ __half g_w2p[NE * HID * DOUT];       // gemm2 B, fragment-packed
__device__ __half g_h  [(size_t)NE * TOK * HID]; // H row-major (gemm2 A)

// gemm1 SMEM (halves)
constexpr int H_AS0 = 0, H_AS1 = CH, H_BS0 = 2 * CH, H_BS1 = 3 * CH;
constexpr int G1_BYTES = 4 * CH * 2;            // 32768

// gemm2 SMEM (halves): A row-major padded LDH=40, B packed
constexpr int LDH   = 40;
constexpr int G2_A0 = 0;
constexpr int G2_A1 = M * LDH;                  // 5120
constexpr int G2_B0 = 2 * M * LDH;              // 10240
constexpr int G2_B1 = G2_B0 + CH;               // 14336
constexpr int G2_BYTES = (G2_B1 + CH) * 2;      // 36864

// ---------------------------------------------------------------------------
DEVINL uint32_t smem_u32(const void* p) {
    uint32_t a;
    asm("{ .reg .u64 t; cvta.to.shared.u64 t, %1; cvt.u32.u64 %0, t; }"
        : "=r"(a) : "l"(p));
    return a;
}

DEVINL void cp16(uint32_t dst, const void* src) {
    asm volatile("cp.async.cg.shared.global [%0], [%1], 16;"
                 :: "r"(dst), "l"(src) : "memory");
}
DEVINL void cp_commit() { asm volatile("cp.async.commit_group;" ::: "memory"); }
template <int N>
DEVINL void cp_wait() { asm volatile("cp.async.wait_group %0;" :: "n"(N) : "memory"); }

DEVINL void mma16(float* c, uint4 a, uint2 b) {
    asm volatile(
        "mma.sync.aligned.m16n8k16.row.col.f32.f16.f16.f32 "
        "{%0,%1,%2,%3}, {%4,%5,%6,%7}, {%8,%9}, {%0,%1,%2,%3};"
        : "+f"(c[0]), "+f"(c[1]), "+f"(c[2]), "+f"(c[3])
        : "r"(a.x), "r"(a.y), "r"(a.z), "r"(a.w), "r"(b.x), "r"(b.y));
}

DEVINL float gelu_exact(float v) {
    return 0.5f * v * (1.0f + erff(v * 0.70710678118654752f));
}

// ---------------------------------------------------------------------------
// Packing prep kernels (f32 -> fp16, mma m16n8k16 fragment order).
// A-chunk (per tile,kc; 4096 halves): ((mblk*2+ks)*32 + lane)*8 + j
//   j: a0={(tq,2tr),(tq,2tr+1)} a1={+8row} a2={+8col} a3={+8row,+8col}
// B-chunk (4096 halves): ((ks*16+nblk)*32 + lane)*4 + j
//   j: b0={(2tr,n),(2tr+1,n)} b1={(2tr+8,n),(2tr+9,n)}
// ---------------------------------------------------------------------------
__global__ void pack_x_kernel(const float* __restrict__ x) {
    int i = blockIdx.x * blockDim.x + threadIdx.x;      // uint4 index (8 halves)
    if (i >= TOK * DIM / 8) return;
    int chunk = i >> 9;
    int tile = chunk >> 4, kc = chunk & 15;
    int inner = i & 511;
    int mblk = inner >> 6;
    int ks   = (inner >> 5) & 1;
    int lane = inner & 31;
    int tq = lane >> 2, tr = lane & 3;
    size_t mb = (size_t)tile * 128 + mblk * 16 + tq;
    int c0 = kc * 32 + ks * 16 + 2 * tr;
    __half h[8];
    h[0] = __float2half_rn(x[mb * DIM + c0]);
    h[1] = __float2half_rn(x[mb * DIM + c0 + 1]);
    h[2] = __float2half_rn(x[(mb + 8) * DIM + c0]);
    h[3] = __float2half_rn(x[(mb + 8) * DIM + c0 + 1]);
    h[4] = __float2half_rn(x[mb * DIM + c0 + 8]);
    h[5] = __float2half_rn(x[mb * DIM + c0 + 9]);
    h[6] = __float2half_rn(x[(mb + 8) * DIM + c0 + 8]);
    h[7] = __float2half_rn(x[(mb + 8) * DIM + c0 + 9]);
    reinterpret_cast<uint4*>(g_xa)[i] = *reinterpret_cast<uint4*>(h);
}

__global__ void pack_w1_kernel(const float* __restrict__ w1) {
    int i = blockIdx.x * blockDim.x + threadIdx.x;      // uint2 index (4 halves)
    if (i >= NE * DIM * HID / 4) return;
    int chunk = i >> 10;
    int e  = chunk >> 6;
    int nt = (chunk >> 4) & 3;
    int kc = chunk & 15;
    int inner = i & 1023;
    int ks   = inner >> 9;
    int nblk = (inner >> 5) & 15;
    int lane = inner & 31;
    int tq = lane >> 2, tr = lane & 3;
    int r0 = kc * 32 + ks * 16 + 2 * tr;
    int nb = nt * 128 + nblk * 8 + tq;
    const float* we = w1 + (size_t)e * DIM * HID;
    __half h[4];
    h[0] = __float2half_rn(we[(size_t)r0 * HID + nb]);
    h[1] = __float2half_rn(we[(size_t)(r0 + 1) * HID + nb]);
    h[2] = __float2half_rn(we[(size_t)(r0 + 8) * HID + nb]);
    h[3] = __float2half_rn(we[(size_t)(r0 + 9) * HID + nb]);
    reinterpret_cast<uint2*>(g_w1p)[i] = *reinterpret_cast<uint2*>(h);
}

__global__ void pack_w2_kernel(const float* __restrict__ w2) {
    int i = blockIdx.x * blockDim.x + threadIdx.x;      // uint2 index
    if (i >= NE * HID * DOUT / 4) return;
    int chunk = i >> 10;
    int e  = chunk >> 4;
    int kc = chunk & 15;
    int inner = i & 1023;
    int ks   = inner >> 9;
    int nblk = (inner >> 5) & 15;
    int lane = inner & 31;
    int tq = lane >> 2, tr = lane & 3;
    int r0 = kc * 32 + ks * 16 + 2 * tr;
    int nb = nblk * 8 + tq;
    const float* we = w2 + (size_t)e * HID * DOUT;
    __half h[4];
    h[0] = __float2half_rn(we[(size_t)r0 * DOUT + nb]);
    h[1] = __float2half_rn(we[(size_t)(r0 + 1) * DOUT + nb]);
    h[2] = __float2half_rn(we[(size_t)(r0 + 8) * DOUT + nb]);
    h[3] = __float2half_rn(we[(size_t)(r0 + 9) * DOUT + nb]);
    reinterpret_cast<uint2*>(g_w2p)[i] = *reinterpret_cast<uint2*>(h);
}

// ---------------------------------------------------------------------------
// copy helpers (256 threads)
// ---------------------------------------------------------------------------
DEVINL void copy_chunk8k(uint32_t sbase, int tid, const __half* __restrict__ src) {
#pragma unroll
    for (int i = 0; i < 2; i++) {
        int idx = tid + i * 256;              // 0..511 x 16B = 8KB
        cp16(sbase + (uint32_t)idx * 16, src + (size_t)idx * 8);
    }
}
DEVINL void copy_a_rows(uint32_t sbase, int tid, const __half* __restrict__ src) {
#pragma unroll
    for (int i = 0; i < 2; i++) {
        int idx = tid + i * 256;              // 0..511
        int row = idx >> 2;                   // 0..127
        int v   = idx & 3;                    // 16B unit (8 halves)
        cp16(sbase + (uint32_t)(row * LDH + v * 8) * 2,
             src + (size_t)row * HID + v * 8);
    }
}

// ---------------------------------------------------------------------------
// Kernel A: H = gelu(X @ W1) — fully packed fp16 operands.
// grid (NE*4, 64), 256 threads, warp grid 4x2 (tile 32x64)
// ---------------------------------------------------------------------------
__global__ void __launch_bounds__(256, 2)
gemm1_gelu_kernel() {
    extern __shared__ __align__(16) __half smh[];
    const uint32_t sb = smem_u32(smh);

    const int tid = threadIdx.x;
    const int wid = tid >> 5, lid = tid & 31;
    const int wr = wid >> 1, wc = wid & 1;
    const int tq = lid >> 2, tr = lid & 3;

    const int e    = blockIdx.x & (NE - 1);
    const int nt   = blockIdx.x >> 4;
    const int tile = blockIdx.y;

    const __half* a_g = g_xa  + (size_t)tile * NKC * CH;
    const __half* b_g = g_w1p + (size_t)(e * 4 + nt) * NKC * CH;

    float c[2][8][4];
#pragma unroll
    for (int mi = 0; mi < 2; mi++)
#pragma unroll
        for (int ni = 0; ni < 8; ni++)
#pragma unroll
            for (int j = 0; j < 4; j++) c[mi][ni][j] = 0.f;

    copy_chunk8k(sb + H_AS0 * 2, tid, a_g);
    copy_chunk8k(sb + H_BS0 * 2, tid, b_g);
    cp_commit();

    for (int kc = 0; kc < NKC; kc++) {
        if (kc + 1 < NKC) {
            copy_chunk8k(sb + (((kc + 1) & 1) ? H_AS1 : H_AS0) * 2, tid,
                         a_g + (size_t)(kc + 1) * CH);
            copy_chunk8k(sb + (((kc + 1) & 1) ? H_BS1 : H_BS0) * 2, tid,
                         b_g + (size_t)(kc + 1) * CH);
            cp_commit();
            cp_wait<1>();
        } else {
            cp_wait<0>();
        }
        __syncthreads();

        const __half* Af = smh + ((kc & 1) ? H_AS1 : H_AS0);
        const __half* Bf = smh + ((kc & 1) ? H_BS1 : H_BS0);
#pragma unroll
        for (int ks = 0; ks < 2; ks++) {
            uint4 a[2];
            uint2 b[8];
#pragma unroll
            for (int mi = 0; mi < 2; mi++)
                a[mi] = *reinterpret_cast<const uint4*>(
                    Af + ((wr * 2 + mi) * 2 + ks) * 256 + lid * 8);
#pragma unroll
            for (int ni = 0; ni < 8; ni++)
                b[ni] = *reinterpret_cast<const uint2*>(
                    Bf + (ks * 16 + wc * 8 + ni) * 128 + lid * 4);
#pragma unroll
            for (int mi = 0; mi < 2; mi++)
#pragma unroll
                for (int ni = 0; ni < 8; ni++)
                    mma16(c[mi][ni], a[mi], b[ni]);
        }
        __syncthreads();
    }

    // epilogue: gelu -> fp16 -> H row-major
    __half* hg = g_h + ((size_t)e * TOK + (size_t)tile * M) * HID + nt * 128;
#pragma unroll
    for (int mi = 0; mi < 2; mi++) {
        const int m0 = wr * 32 + mi * 16;
#pragma unroll
        for (int ni = 0; ni < 8; ni++) {
            const int n0 = wc * 64 + ni * 8 + 2 * tr;
            __half2 v0, v1;
            v0.x = __float2half_rn(gelu_exact(c[mi][ni][0]));
            v0.y = __float2half_rn(gelu_exact(c[mi][ni][1]));
            v1.x = __float2half_rn(gelu_exact(c[mi][ni][2]));
            v1.y = __float2half_rn(gelu_exact(c[mi][ni][3]));
            *reinterpret_cast<__half2*>(hg + (size_t)(m0 + tq) * HID + n0)     = v0;
            *reinterpret_cast<__half2*>(hg + (size_t)(m0 + tq + 8) * HID + n0) = v1;
        }
    }
}

// ---------------------------------------------------------------------------
// Kernel B: out = H @ W2 — A row-major halves (LDH=40), B packed.
// grid (16, 64), 256 threads, warp grid 4x2
// ---------------------------------------------------------------------------
__global__ void __launch_bounds__(256, 2)
gemm2_kernel(float* __restrict__ out) {
    extern __shared__ __align__(16) __half smh[];
    const uint32_t sb = smem_u32(smh);

    const int tid = threadIdx.x;
    const int wid = tid >> 5, lid = tid & 31;
    const int wr = wid >> 1, wc = wid & 1;
    const int tq = lid >> 2, tr = lid & 3;

    const int e    = blockIdx.x;
    const int tile = blockIdx.y;

    const __half* a_g = g_h   + ((size_t)e * TOK + (size_t)tile * M) * HID;
    const __half* b_g = g_w2p + (size_t)e * NKC * CH;

    float c[2][8][4];
#pragma unroll
    for (int mi = 0; mi < 2; mi++)
#pragma unroll
        for (int ni = 0; ni < 8; ni++)
#pragma unroll
            for (int j = 0; j < 4; j++) c[mi][ni][j] = 0.f;

    copy_a_rows(sb + G2_A0 * 2, tid, a_g);
    copy_chunk8k(sb + G2_B0 * 2, tid, b_g);
    cp_commit();

    for (int kc = 0; kc < NKC; kc++) {
        if (kc + 1 < NKC) {
            copy_a_rows(sb + (((kc + 1) & 1) ? G2_A1 : G2_A0) * 2, tid,
                        a_g + (kc + 1) * KC);
            copy_chunk8k(sb + (((kc + 1) & 1) ? G2_B1 : G2_B0) * 2, tid,
                        b_g + (size_t)(kc + 1) * CH);
            cp_commit();
            cp_wait<1>();
        } else {
            cp_wait<0>();
        }
        __syncthreads();

        const __half* Ah = smh + ((kc & 1) ? G2_A1 : G2_A0);
        const __half* Bf = smh + ((kc & 1) ? G2_B1 : G2_B0);
#pragma unroll
        for (int ks = 0; ks < 2; ks++) {
            const int k0 = ks * 16 + 2 * tr;
            uint4 a[2];
            uint2 b[8];
#pragma unroll
            for (int mi = 0; mi < 2; mi++) {
                const int m0 = wr * 32 + mi * 16;
                a[mi].x = *reinterpret_cast<const uint32_t*>(Ah + (m0 + tq) * LDH + k0);
                a[mi].y = *reinterpret_cast<const uint32_t*>(Ah + (m0 + tq + 8) * LDH + k0);
                a[mi].z = *reinterpret_cast<const uint32_t*>(Ah + (m0 + tq) * LDH + k0 + 8);
                a[mi].w = *reinterpret_cast<const uint32_t*>(Ah + (m0 + tq + 8) * LDH + k0 + 8);
            }
#pragma unroll
            for (int ni = 0; ni < 8; ni++)
                b[ni] = *reinterpret_cast<const uint2*>(
                    Bf + (ks * 16 + wc * 8 + ni) * 128 + lid * 4);
#pragma unroll
            for (int mi = 0; mi < 2; mi++)
#pragma unroll
                for (int ni = 0; ni < 8; ni++)
                    mma16(c[mi][ni], a[mi], b[ni]);
        }
        __syncthreads();
    }

    // epilogue: scatter to out[(tok*128 + d)*16 + e]
#pragma unroll
    for (int mi = 0; mi < 2; mi++) {
        const size_t tok0 = (size_t)tile * M + wr * 32 + mi * 16 + tq;
#pragma unroll
        for (int ni = 0; ni < 8; ni++) {
            const int d0 = wc * 64 + ni * 8 + 2 * tr;
            out[(tok0 * DOUT + d0) * NE + e]           = c[mi][ni][0];
            out[(tok0 * DOUT + d0 + 1) * NE + e]       = c[mi][ni][1];
            out[((tok0 + 8) * DOUT + d0) * NE + e]     = c[mi][ni][2];
            out[((tok0 + 8) * DOUT + d0 + 1) * NE + e] = c[mi][ni][3];
        }
    }
}

// ---------------------------------------------------------------------------
extern "C" void kernel_launch(void* const* d_in, const int* in_sizes, int n_in,
                              void* d_out, int out_size) {
    const float* x  = (const float*)d_in[0];
    const float* w1 = (const float*)d_in[1];
    const float* w2 = (const float*)d_in[2];
    float* out      = (float*)d_out;

    constexpr int NX  = TOK * DIM / 8;
    constexpr int NW1 = NE * DIM * HID / 4;
    constexpr int NW2 = NE * HID * DOUT / 4;
    pack_x_kernel <<<(NX  + 255) / 256, 256>>>(x);
    pack_w1_kernel<<<(NW1 + 255) / 256, 256>>>(w1);
    pack_w2_kernel<<<(NW2 + 255) / 256, 256>>>(w2);

    cudaFuncSetAttribute(gemm1_gelu_kernel,
                         cudaFuncAttributeMaxDynamicSharedMemorySize, G1_BYTES);
    cudaFuncSetAttribute(gemm2_kernel,
                         cudaFuncAttributeMaxDynamicSharedMemorySize, G2_BYTES);

    gemm1_gelu_kernel<<<dim3(NE * (HID / 128), TOK / M), 256, G1_BYTES>>>();
    gemm2_kernel<<<dim3(NE, TOK / M), 256, G2_BYTES>>>(out);
}

// round 12
// speedup vs baseline: 1.6687x; 1.0552x over previous
#include <cuda_runtime.h>
#include <cuda_fp16.h>
#include <cstdint>

// ============================================================================
// Experts — two-stage GEMM via mma.sync fp16 m16n8k16 (sm_103 base target)
// Round 11: KC 32->64 (8 mainloop iterations instead of 16). Packed chunk
// order makes two consecutive 8KB chunks contiguous, so prep is unchanged
// and each buffer refill is one 16KB cp.async burst. Halves barrier count,
// doubles the schedulable region per iteration.
//   x  : [4,2048,512] f32 ; w1 : [16,512,512] ; w2 : [16,512,128]
//   out: [4,2048,128,16] f32, out[(tok*128 + d)*16 + e]
// ============================================================================

#define DEVINL __device__ __forceinline__

constexpr int NE   = 16;
constexpr int DIM  = 512;
constexpr int HID  = 512;
constexpr int DOUT = 128;
constexpr int TOK  = 8192;

constexpr int M    = 128;
constexpr int CH   = 4096;           // halves per packed 8KB sub-chunk
constexpr int KC2  = 64;             // k per mainloop iteration
constexpr int NK2  = DIM / KC2;      // 8
constexpr int BIG  = 2 * CH;         // halves per 16KB buffer

// packed half buffers (layouts identical to round 10)
__device__ __half g_xa [TOK * DIM];
__device__ __half g_w1p[NE * DIM * HID];
__device__ __half g_w2p[NE * HID * DOUT];
__device__ __half g_h  [(size_t)NE * TOK * HID];

// gemm1 SMEM (halves): 2x(A 16KB) + 2x(B 16KB) = 64KB
constexpr int H_A0 = 0, H_A1 = BIG, H_B0 = 2 * BIG, H_B1 = 3 * BIG;
constexpr int G1_BYTES = 4 * BIG * 2;            // 65536

// gemm2 SMEM (halves): A row-major 128x64 pad LDH2=72, B packed 16KB, x2
constexpr int LDH2  = 72;
constexpr int G2_A0 = 0;
constexpr int G2_A1 = M * LDH2;                  // 9216
constexpr int G2_B0 = 2 * M * LDH2;              // 18432
constexpr int G2_B1 = G2_B0 + BIG;               // 26624
constexpr int G2_BYTES = (G2_B1 + BIG) * 2;      // 69632

// ---------------------------------------------------------------------------
DEVINL uint32_t smem_u32(const void* p) {
    uint32_t a;
    asm("{ .reg .u64 t; cvta.to.shared.u64 t, %1; cvt.u32.u64 %0, t; }"
        : "=r"(a) : "l"(p));
    return a;
}

DEVINL void cp16(uint32_t dst, const void* src) {
    asm volatile("cp.async.cg.shared.global [%0], [%1], 16;"
                 :: "r"(dst), "l"(src) : "memory");
}
DEVINL void cp_commit() { asm volatile("cp.async.commit_group;" ::: "memory"); }
template <int N>
DEVINL void cp_wait() { asm volatile("cp.async.wait_group %0;" :: "n"(N) : "memory"); }

DEVINL void mma16(float* c, uint4 a, uint2 b) {
    asm volatile(
        "mma.sync.aligned.m16n8k16.row.col.f32.f16.f16.f32 "
        "{%0,%1,%2,%3}, {%4,%5,%6,%7}, {%8,%9}, {%0,%1,%2,%3};"
        : "+f"(c[0]), "+f"(c[1]), "+f"(c[2]), "+f"(c[3])
        : "r"(a.x), "r"(a.y), "r"(a.z), "r"(a.w), "r"(b.x), "r"(b.y));
}

DEVINL float gelu_exact(float v) {
    return 0.5f * v * (1.0f + erff(v * 0.70710678118654752f));
}

// ---------------------------------------------------------------------------
// Packing prep kernels (identical to round 10).
// ---------------------------------------------------------------------------
__global__ void pack_x_kernel(const float* __restrict__ x) {
    int i = blockIdx.x * blockDim.x + threadIdx.x;      // uint4 index (8 halves)
    if (i >= TOK * DIM / 8) return;
    int chunk = i >> 9;
    int tile = chunk >> 4, kc = chunk & 15;
    int inner = i & 511;
    int mblk = inner >> 6;
    int ks   = (inner >> 5) & 1;
    int lane = inner & 31;
    int tq = lane >> 2, tr = lane & 3;
    size_t mb = (size_t)tile * 128 + mblk * 16 + tq;
    int c0 = kc * 32 + ks * 16 + 2 * tr;
    __half h[8];
    h[0] = __float2half_rn(x[mb * DIM + c0]);
    h[1] = __float2half_rn(x[mb * DIM + c0 + 1]);
    h[2] = __float2half_rn(x[(mb + 8) * DIM + c0]);
    h[3] = __float2half_rn(x[(mb + 8) * DIM + c0 + 1]);
    h[4] = __float2half_rn(x[mb * DIM + c0 + 8]);
    h[5] = __float2half_rn(x[mb * DIM + c0 + 9]);
    h[6] = __float2half_rn(x[(mb + 8) * DIM + c0 + 8]);
    h[7] = __float2half_rn(x[(mb + 8) * DIM + c0 + 9]);
    reinterpret_cast<uint4*>(g_xa)[i] = *reinterpret_cast<uint4*>(h);
}

__global__ void pack_w1_kernel(const float* __restrict__ w1) {
    int i = blockIdx.x * blockDim.x + threadIdx.x;      // uint2 index (4 halves)
    if (i >= NE * DIM * HID / 4) return;
    int chunk = i >> 10;
    int e  = chunk >> 6;
    int nt = (chunk >> 4) & 3;
    int kc = chunk & 15;
    int inner = i & 1023;
    int ks   = inner >> 9;
    int nblk = (inner >> 5) & 15;
    int lane = inner & 31;
    int tq = lane >> 2, tr = lane & 3;
    int r0 = kc * 32 + ks * 16 + 2 * tr;
    int nb = nt * 128 + nblk * 8 + tq;
    const float* we = w1 + (size_t)e * DIM * HID;
    __half h[4];
    h[0] = __float2half_rn(we[(size_t)r0 * HID + nb]);
    h[1] = __float2half_rn(we[(size_t)(r0 + 1) * HID + nb]);
    h[2] = __float2half_rn(we[(size_t)(r0 + 8) * HID + nb]);
    h[3] = __float2half_rn(we[(size_t)(r0 + 9) * HID + nb]);
    reinterpret_cast<uint2*>(g_w1p)[i] = *reinterpret_cast<uint2*>(h);
}

__global__ void pack_w2_kernel(const float* __restrict__ w2) {
    int i = blockIdx.x * blockDim.x + threadIdx.x;      // uint2 index
    if (i >= NE * HID * DOUT / 4) return;
    int chunk = i >> 10;
    int e  = chunk >> 4;
    int kc = chunk & 15;
    int inner = i & 1023;
    int ks   = inner >> 9;
    int nblk = (inner >> 5) & 15;
    int lane = inner & 31;
    int tq = lane >> 2, tr = lane & 3;
    int r0 = kc * 32 + ks * 16 + 2 * tr;
    int nb = nblk * 8 + tq;
    const float* we = w2 + (size_t)e * HID * DOUT;
    __half h[4];
    h[0] = __float2half_rn(we[(size_t)r0 * DOUT + nb]);
    h[1] = __float2half_rn(we[(size_t)(r0 + 1) * DOUT + nb]);
    h[2] = __float2half_rn(we[(size_t)(r0 + 8) * DOUT + nb]);
    h[3] = __float2half_rn(we[(size_t)(r0 + 9) * DOUT + nb]);
    reinterpret_cast<uint2*>(g_w2p)[i] = *reinterpret_cast<uint2*>(h);
}

// ---------------------------------------------------------------------------
// copy helpers (256 threads)
// ---------------------------------------------------------------------------
DEVINL void copy_16k(uint32_t sbase, int tid, const __half* __restrict__ src) {
#pragma unroll
    for (int i = 0; i < 4; i++) {
        int idx = tid + i * 256;              // 0..1023 x 16B = 16KB
        cp16(sbase + (uint32_t)idx * 16, src + (size_t)idx * 8);
    }
}
DEVINL void copy_a_rows64(uint32_t sbase, int tid, const __half* __restrict__ src) {
#pragma unroll
    for (int i = 0; i < 4; i++) {
        int idx = tid + i * 256;              // 0..1023
        int row = idx >> 3;                   // 0..127
        int v   = idx & 7;                    // 16B unit (8 halves)
        cp16(sbase + (uint32_t)(row * LDH2 + v * 8) * 2,
             src + (size_t)row * HID + v * 8);
    }
}

// ---------------------------------------------------------------------------
// Kernel A: H = gelu(X @ W1) — fully packed fp16 operands, KC=64.
// grid (NE*4, 64), 256 threads, warp grid 4x2 (tile 32x64)
// ---------------------------------------------------------------------------
__global__ void __launch_bounds__(256, 2)
gemm1_gelu_kernel() {
    extern __shared__ __align__(16) __half smh[];
    const uint32_t sb = smem_u32(smh);

    const int tid = threadIdx.x;
    const int wid = tid >> 5, lid = tid & 31;
    const int wr = wid >> 1, wc = wid & 1;
    const int tq = lid >> 2, tr = lid & 3;

    const int e    = blockIdx.x & (NE - 1);
    const int nt   = blockIdx.x >> 4;
    const int tile = blockIdx.y;

    const __half* a_g = g_xa  + (size_t)tile * NK2 * BIG;
    const __half* b_g = g_w1p + (size_t)(e * 4 + nt) * NK2 * BIG;

    float c[2][8][4];
#pragma unroll
    for (int mi = 0; mi < 2; mi++)
#pragma unroll
        for (int ni = 0; ni < 8; ni++)
#pragma unroll
            for (int j = 0; j < 4; j++) c[mi][ni][j] = 0.f;

    copy_16k(sb + H_A0 * 2, tid, a_g);
    copy_16k(sb + H_B0 * 2, tid, b_g);
    cp_commit();

    for (int kc = 0; kc < NK2; kc++) {
        if (kc + 1 < NK2) {
            copy_16k(sb + (((kc + 1) & 1) ? H_A1 : H_A0) * 2, tid,
                     a_g + (size_t)(kc + 1) * BIG);
            copy_16k(sb + (((kc + 1) & 1) ? H_B1 : H_B0) * 2, tid,
                     b_g + (size_t)(kc + 1) * BIG);
            cp_commit();
            cp_wait<1>();
        } else {
            cp_wait<0>();
        }
        __syncthreads();

        const __half* Af = smh + ((kc & 1) ? H_A1 : H_A0);
        const __half* Bf = smh + ((kc & 1) ? H_B1 : H_B0);
#pragma unroll
        for (int s = 0; s < 4; s++) {
            const int sub = s >> 1, ks = s & 1;
            const __half* Afs = Af + sub * CH;
            const __half* Bfs = Bf + sub * CH;
            uint4 a[2];
            uint2 b[8];
#pragma unroll
            for (int mi = 0; mi < 2; mi++)
                a[mi] = *reinterpret_cast<const uint4*>(
                    Afs + ((wr * 2 + mi) * 2 + ks) * 256 + lid * 8);
#pragma unroll
            for (int ni = 0; ni < 8; ni++)
                b[ni] = *reinterpret_cast<const uint2*>(
                    Bfs + (ks * 16 + wc * 8 + ni) * 128 + lid * 4);
#pragma unroll
            for (int mi = 0; mi < 2; mi++)
#pragma unroll
                for (int ni = 0; ni < 8; ni++)
                    mma16(c[mi][ni], a[mi], b[ni]);
        }
        __syncthreads();
    }

    // epilogue: gelu -> fp16 -> H row-major
    __half* hg = g_h + ((size_t)e * TOK + (size_t)tile * M) * HID + nt * 128;
#pragma unroll
    for (int mi = 0; mi < 2; mi++) {
        const int m0 = wr * 32 + mi * 16;
#pragma unroll
        for (int ni = 0; ni < 8; ni++) {
            const int n0 = wc * 64 + ni * 8 + 2 * tr;
            __half2 v0, v1;
            v0.x = __float2half_rn(gelu_exact(c[mi][ni][0]));
            v0.y = __float2half_rn(gelu_exact(c[mi][ni][1]));
            v1.x = __float2half_rn(gelu_exact(c[mi][ni][2]));
            v1.y = __float2half_rn(gelu_exact(c[mi][ni][3]));
            *reinterpret_cast<__half2*>(hg + (size_t)(m0 + tq) * HID + n0)     = v0;
            *reinterpret_cast<__half2*>(hg + (size_t)(m0 + tq + 8) * HID + n0) = v1;
        }
    }
}

// ---------------------------------------------------------------------------
// Kernel B: out = H @ W2 — A row-major halves (LDH2=72), B packed, KC=64.
// grid (16, 64), 256 threads, warp grid 4x2
// ---------------------------------------------------------------------------
__global__ void __launch_bounds__(256, 2)
gemm2_kernel(float* __restrict__ out) {
    extern __shared__ __align__(16) __half smh[];
    const uint32_t sb = smem_u32(smh);

    const int tid = threadIdx.x;
    const int wid = tid >> 5, lid = tid & 31;
    const int wr = wid >> 1, wc = wid & 1;
    const int tq = lid >> 2, tr = lid & 3;

    const int e    = blockIdx.x;
    const int tile = blockIdx.y;

    const __half* a_g = g_h   + ((size_t)e * TOK + (size_t)tile * M) * HID;
    const __half* b_g = g_w2p + (size_t)e * NK2 * BIG;

    float c[2][8][4];
#pragma unroll
    for (int mi = 0; mi < 2; mi++)
#pragma unroll
        for (int ni = 0; ni < 8; ni++)
#pragma unroll
            for (int j = 0; j < 4; j++) c[mi][ni][j] = 0.f;

    copy_a_rows64(sb + G2_A0 * 2, tid, a_g);
    copy_16k(sb + G2_B0 * 2, tid, b_g);
    cp_commit();

    for (int kc = 0; kc < NK2; kc++) {
        if (kc + 1 < NK2) {
            copy_a_rows64(sb + (((kc + 1) & 1) ? G2_A1 : G2_A0) * 2, tid,
                          a_g + (kc + 1) * KC2);
            copy_16k(sb + (((kc + 1) & 1) ? G2_B1 : G2_B0) * 2, tid,
                     b_g + (size_t)(kc + 1) * BIG);
            cp_commit();
            cp_wait<1>();
        } else {
            cp_wait<0>();
        }
        __syncthreads();

        const __half* Ah = smh + ((kc & 1) ? G2_A1 : G2_A0);
        const __half* Bf = smh + ((kc & 1) ? G2_B1 : G2_B0);
#pragma unroll
        for (int s = 0; s < 4; s++) {
            const int sub = s >> 1, ks = s & 1;
            const int k0 = sub * 32 + ks * 16 + 2 * tr;
            const __half* Bfs = Bf + sub * CH;
            uint4 a[2];
            uint2 b[8];
#pragma unroll
            for (int mi = 0; mi < 2; mi++) {
                const int m0 = wr * 32 + mi * 16;
                a[mi].x = *reinterpret_cast<const uint32_t*>(Ah + (m0 + tq) * LDH2 + k0);
                a[mi].y = *reinterpret_cast<const uint32_t*>(Ah + (m0 + tq + 8) * LDH2 + k0);
                a[mi].z = *reinterpret_cast<const uint32_t*>(Ah + (m0 + tq) * LDH2 + k0 + 8);
                a[mi].w = *reinterpret_cast<const uint32_t*>(Ah + (m0 + tq + 8) * LDH2 + k0 + 8);
            }
#pragma unroll
            for (int ni = 0; ni < 8; ni++)
                b[ni] = *reinterpret_cast<const uint2*>(
                    Bfs + (ks * 16 + wc * 8 + ni) * 128 + lid * 4);
#pragma unroll
            for (int mi = 0; mi < 2; mi++)
#pragma unroll
                for (int ni = 0; ni < 8; ni++)
                    mma16(c[mi][ni], a[mi], b[ni]);
        }
        __syncthreads();
    }

    // epilogue: scatter to out[(tok*128 + d)*16 + e]
#pragma unroll
    for (int mi = 0; mi < 2; mi++) {
        const size_t tok0 = (size_t)tile * M + wr * 32 + mi * 16 + tq;
#pragma unroll
        for (int ni = 0; ni < 8; ni++) {
            const int d0 = wc * 64 + ni * 8 + 2 * tr;
            out[(tok0 * DOUT + d0) * NE + e]           = c[mi][ni][0];
            out[(tok0 * DOUT + d0 + 1) * NE + e]       = c[mi][ni][1];
            out[((tok0 + 8) * DOUT + d0) * NE + e]     = c[mi][ni][2];
            out[((tok0 + 8) * DOUT + d0 + 1) * NE + e] = c[mi][ni][3];
        }
    }
}

// ---------------------------------------------------------------------------
extern "C" void kernel_launch(void* const* d_in, const int* in_sizes, int n_in,
                              void* d_out, int out_size) {
    const float* x  = (const float*)d_in[0];
    const float* w1 = (const float*)d_in[1];
    const float* w2 = (const float*)d_in[2];
    float* out      = (float*)d_out;

    constexpr int NX  = TOK * DIM / 8;
    constexpr int NW1 = NE * DIM * HID / 4;
    constexpr int NW2 = NE * HID * DOUT / 4;
    pack_x_kernel <<<(NX  + 255) / 256, 256>>>(x);
    pack_w1_kernel<<<(NW1 + 255) / 256, 256>>>(w1);
    pack_w2_kernel<<<(NW2 + 255) / 256, 256>>>(w2);

    cudaFuncSetAttribute(gemm1_gelu_kernel,
                         cudaFuncAttributeMaxDynamicSharedMemorySize, G1_BYTES);
    cudaFuncSetAttribute(gemm2_kernel,
                         cudaFuncAttributeMaxDynamicSharedMemorySize, G2_BYTES);

    gemm1_gelu_kernel<<<dim3(NE * (HID / 128), TOK / M), 256, G1_BYTES>>>();
    gemm2_kernel<<<dim3(NE, TOK / M), 256, G2_BYTES>>>(out);
}

// round 15
// speedup vs baseline: 1.6736x; 1.0030x over previous
#include <cuda_runtime.h>
#include <cuda_fp16.h>
#include <cstdint>

// ============================================================================
// Experts — two-stage GEMM via mma.sync fp16 m16n8k16 (sm_103 base target)
// Round 12: gemm1 epilogue writes H directly in gemm2's fragment-packed A
// layout, so gemm2's mainloop becomes identical to gemm1's (LDS.128 A frags
// instead of 8 scalar LDS.32 per substep).
//   x  : [4,2048,512] f32 ; w1 : [16,512,512] ; w2 : [16,512,128]
//   out: [4,2048,128,16] f32, out[(tok*128 + d)*16 + e]
// ============================================================================

#define DEVINL __device__ __forceinline__

constexpr int NE   = 16;
constexpr int DIM  = 512;
constexpr int HID  = 512;
constexpr int DOUT = 128;
constexpr int TOK  = 8192;

constexpr int M    = 128;
constexpr int CH   = 4096;           // halves per packed 8KB sub-chunk
constexpr int KC2  = 64;             // k per mainloop iteration
constexpr int NK2  = DIM / KC2;      // 8
constexpr int BIG  = 2 * CH;         // halves per 16KB buffer

// packed half buffers
__device__ __half g_xa [TOK * DIM];              // gemm1 A, fragment-packed
__device__ __half g_w1p[NE * DIM * HID];         // gemm1 B, fragment-packed
__device__ __half g_w2p[NE * HID * DOUT];        // gemm2 B, fragment-packed
__device__ __half g_ha [(size_t)NE * TOK * HID]; // H, fragment-packed A for gemm2

// SMEM (halves): 2x(A 16KB) + 2x(B 16KB) = 64KB — both kernels
constexpr int H_A0 = 0, H_A1 = BIG, H_B0 = 2 * BIG, H_B1 = 3 * BIG;
constexpr int G_BYTES = 4 * BIG * 2;             // 65536

// ---------------------------------------------------------------------------
DEVINL uint32_t smem_u32(const void* p) {
    uint32_t a;
    asm("{ .reg .u64 t; cvta.to.shared.u64 t, %1; cvt.u32.u64 %0, t; }"
        : "=r"(a) : "l"(p));
    return a;
}

DEVINL void cp16(uint32_t dst, const void* src) {
    asm volatile("cp.async.cg.shared.global [%0], [%1], 16;"
                 :: "r"(dst), "l"(src) : "memory");
}
DEVINL void cp_commit() { asm volatile("cp.async.commit_group;" ::: "memory"); }
template <int N>
DEVINL void cp_wait() { asm volatile("cp.async.wait_group %0;" :: "n"(N) : "memory"); }

DEVINL void mma16(float* c, uint4 a, uint2 b) {
    asm volatile(
        "mma.sync.aligned.m16n8k16.row.col.f32.f16.f16.f32 "
        "{%0,%1,%2,%3}, {%4,%5,%6,%7}, {%8,%9}, {%0,%1,%2,%3};"
        : "+f"(c[0]), "+f"(c[1]), "+f"(c[2]), "+f"(c[3])
        : "r"(a.x), "r"(a.y), "r"(a.z), "r"(a.w), "r"(b.x), "r"(b.y));
}

DEVINL float gelu_exact(float v) {
    return 0.5f * v * (1.0f + erff(v * 0.70710678118654752f));
}

// ---------------------------------------------------------------------------
// Packing prep kernels (identical to rounds 10/11).
// A-chunk (4096 halves): ((mblk*2+ks)*32 + lane)*8 + j
// B-chunk (4096 halves): ((ks*16+nblk)*32 + lane)*4 + j
// ---------------------------------------------------------------------------
__global__ void pack_x_kernel(const float* __restrict__ x) {
    int i = blockIdx.x * blockDim.x + threadIdx.x;      // uint4 index (8 halves)
    if (i >= TOK * DIM / 8) return;
    int chunk = i >> 9;
    int tile = chunk >> 4, kc = chunk & 15;
    int inner = i & 511;
    int mblk = inner >> 6;
    int ks   = (inner >> 5) & 1;
    int lane = inner & 31;
    int tq = lane >> 2, tr = lane & 3;
    size_t mb = (size_t)tile * 128 + mblk * 16 + tq;
    int c0 = kc * 32 + ks * 16 + 2 * tr;
    __half h[8];
    h[0] = __float2half_rn(x[mb * DIM + c0]);
    h[1] = __float2half_rn(x[mb * DIM + c0 + 1]);
    h[2] = __float2half_rn(x[(mb + 8) * DIM + c0]);
    h[3] = __float2half_rn(x[(mb + 8) * DIM + c0 + 1]);
    h[4] = __float2half_rn(x[mb * DIM + c0 + 8]);
    h[5] = __float2half_rn(x[mb * DIM + c0 + 9]);
    h[6] = __float2half_rn(x[(mb + 8) * DIM + c0 + 8]);
    h[7] = __float2half_rn(x[(mb + 8) * DIM + c0 + 9]);
    reinterpret_cast<uint4*>(g_xa)[i] = *reinterpret_cast<uint4*>(h);
}

__global__ void pack_w1_kernel(const float* __restrict__ w1) {
    int i = blockIdx.x * blockDim.x + threadIdx.x;      // uint2 index (4 halves)
    if (i >= NE * DIM * HID / 4) return;
    int chunk = i >> 10;
    int e  = chunk >> 6;
    int nt = (chunk >> 4) & 3;
    int kc = chunk & 15;
    int inner = i & 1023;
    int ks   = inner >> 9;
    int nblk = (inner >> 5) & 15;
    int lane = inner & 31;
    int tq = lane >> 2, tr = lane & 3;
    int r0 = kc * 32 + ks * 16 + 2 * tr;
    int nb = nt * 128 + nblk * 8 + tq;
    const float* we = w1 + (size_t)e * DIM * HID;
    __half h[4];
    h[0] = __float2half_rn(we[(size_t)r0 * HID + nb]);
    h[1] = __float2half_rn(we[(size_t)(r0 + 1) * HID + nb]);
    h[2] = __float2half_rn(we[(size_t)(r0 + 8) * HID + nb]);
    h[3] = __float2half_rn(we[(size_t)(r0 + 9) * HID + nb]);
    reinterpret_cast<uint2*>(g_w1p)[i] = *reinterpret_cast<uint2*>(h);
}

__global__ void pack_w2_kernel(const float* __restrict__ w2) {
    int i = blockIdx.x * blockDim.x + threadIdx.x;      // uint2 index
    if (i >= NE * HID * DOUT / 4) return;
    int chunk = i >> 10;
    int e  = chunk >> 4;
    int kc = chunk & 15;
    int inner = i & 1023;
    int ks   = inner >> 9;
    int nblk = (inner >> 5) & 15;
    int lane = inner & 31;
    int tq = lane >> 2, tr = lane & 3;
    int r0 = kc * 32 + ks * 16 + 2 * tr;
    int nb = nblk * 8 + tq;
    const float* we = w2 + (size_t)e * HID * DOUT;
    __half h[4];
    h[0] = __float2half_rn(we[(size_t)r0 * DOUT + nb]);
    h[1] = __float2half_rn(we[(size_t)(r0 + 1) * DOUT + nb]);
    h[2] = __float2half_rn(we[(size_t)(r0 + 8) * DOUT + nb]);
    h[3] = __float2half_rn(we[(size_t)(r0 + 9) * DOUT + nb]);
    reinterpret_cast<uint2*>(g_w2p)[i] = *reinterpret_cast<uint2*>(h);
}

// ---------------------------------------------------------------------------
DEVINL void copy_16k(uint32_t sbase, int tid, const __half* __restrict__ src) {
#pragma unroll
    for (int i = 0; i < 4; i++) {
        int idx = tid + i * 256;              // 0..1023 x 16B = 16KB
        cp16(sbase + (uint32_t)idx * 16, src + (size_t)idx * 8);
    }
}

// ---------------------------------------------------------------------------
// shared mainloop: both kernels run identical fully-packed pipelines.
// ---------------------------------------------------------------------------
DEVINL void packed_mainloop(const __half* __restrict__ a_g,
                            const __half* __restrict__ b_g,
                            const __half* smh, uint32_t sb, int tid,
                            int wr, int wc, int lid, float c[2][8][4]) {
    copy_16k(sb + H_A0 * 2, tid, a_g);
    copy_16k(sb + H_B0 * 2, tid, b_g);
    cp_commit();

    for (int kc = 0; kc < NK2; kc++) {
        if (kc + 1 < NK2) {
            copy_16k(sb + (((kc + 1) & 1) ? H_A1 : H_A0) * 2, tid,
                     a_g + (size_t)(kc + 1) * BIG);
            copy_16k(sb + (((kc + 1) & 1) ? H_B1 : H_B0) * 2, tid,
                     b_g + (size_t)(kc + 1) * BIG);
            cp_commit();
            cp_wait<1>();
        } else {
            cp_wait<0>();
        }
        __syncthreads();

        const __half* Af = smh + ((kc & 1) ? H_A1 : H_A0);
        const __half* Bf = smh + ((kc & 1) ? H_B1 : H_B0);
#pragma unroll
        for (int s = 0; s < 4; s++) {
            const int sub = s >> 1, ks = s & 1;
            const __half* Afs = Af + sub * CH;
            const __half* Bfs = Bf + sub * CH;
            uint4 a[2];
            uint2 b[8];
#pragma unroll
            for (int mi = 0; mi < 2; mi++)
                a[mi] = *reinterpret_cast<const uint4*>(
                    Afs + ((wr * 2 + mi) * 2 + ks) * 256 + lid * 8);
#pragma unroll
            for (int ni = 0; ni < 8; ni++)
                b[ni] = *reinterpret_cast<const uint2*>(
                    Bfs + (ks * 16 + wc * 8 + ni) * 128 + lid * 4);
#pragma unroll
            for (int mi = 0; mi < 2; mi++)
#pragma unroll
                for (int ni = 0; ni < 8; ni++)
                    mma16(c[mi][ni], a[mi], b[ni]);
        }
        __syncthreads();
    }
}

// ---------------------------------------------------------------------------
// Kernel A: H = gelu(X @ W1); epilogue writes fragment-packed A chunks.
// grid (NE*4, 64), 256 threads, warp grid 4x2 (tile 32x64)
// ---------------------------------------------------------------------------
__global__ void __launch_bounds__(256, 2)
gemm1_gelu_kernel() {
    extern __shared__ __align__(16) __half smh[];
    const uint32_t sb = smem_u32(smh);

    const int tid = threadIdx.x;
    const int wid = tid >> 5, lid = tid & 31;
    const int wr = wid >> 1, wc = wid & 1;

    const int e    = blockIdx.x & (NE - 1);
    const int nt   = blockIdx.x >> 4;
    const int tile = blockIdx.y;

    const __half* a_g = g_xa  + (size_t)tile * NK2 * BIG;
    const __half* b_g = g_w1p + (size_t)(e * 4 + nt) * NK2 * BIG;

    float c[2][8][4];
#pragma unroll
    for (int mi = 0; mi < 2; mi++)
#pragma unroll
        for (int ni = 0; ni < 8; ni++)
#pragma unroll
            for (int j = 0; j < 4; j++) c[mi][ni][j] = 0.f;

    packed_mainloop(a_g, b_g, smh, sb, tid, wr, wc, lid, c);

    // epilogue: gelu -> fp16 -> g_ha in packed-A-chunk layout for gemm2.
    // element (row m, hid col ch) of tile -> chunk kc=ch>>5, ks=(ch>>4)&1,
    // offset = ((mblk*2+ks)*32 + lane)*8 + csel*4 + rsel*2 + parity
    __half* ha = g_ha + ((size_t)(e * 64 + tile) * 16) * CH;
#pragma unroll
    for (int mi = 0; mi < 2; mi++) {
#pragma unroll
        for (int ni = 0; ni < 8; ni++) {
            const int kcp = nt * 4 + wc * 2 + (ni >> 2);
            const int ksp = (ni >> 1) & 1;
            const uint32_t off =
                (uint32_t)((((wr * 2 + mi) * 2 + ksp) * 32 + lid) * 8 + (ni & 1) * 4);
            __half2 v0, v1;
            v0.x = __float2half_rn(gelu_exact(c[mi][ni][0]));
            v0.y = __float2half_rn(gelu_exact(c[mi][ni][1]));
            v1.x = __float2half_rn(gelu_exact(c[mi][ni][2]));
            v1.y = __float2half_rn(gelu_exact(c[mi][ni][3]));
            *reinterpret_cast<__half2*>(ha + (size_t)kcp * CH + off)     = v0;
            *reinterpret_cast<__half2*>(ha + (size_t)kcp * CH + off + 2) = v1;
        }
    }
}

// ---------------------------------------------------------------------------
// Kernel B: out = H @ W2 — fully packed, identical mainloop to gemm1.
// grid (16, 64), 256 threads, warp grid 4x2
// ---------------------------------------------------------------------------
__global__ void __launch_bounds__(256, 2)
gemm2_kernel(float* __restrict__ out) {
    extern __shared__ __align__(16) __half smh[];
    const uint32_t sb = smem_u32(smh);

    const int tid = threadIdx.x;
    const int wid = tid >> 5, lid = tid & 31;
    const int wr = wid >> 1, wc = wid & 1;
    const int tq = lid >> 2, tr = lid & 3;

    const int e    = blockIdx.x;
    const int tile = blockIdx.y;

    const __half* a_g = g_ha  + ((size_t)(e * 64 + tile) * 16) * CH;
    const __half* b_g = g_w2p + (size_t)e * NK2 * BIG;

    float c[2][8][4];
#pragma unroll
    for (int mi = 0; mi < 2; mi++)
#pragma unroll
        for (int ni = 0; ni < 8; ni++)
#pragma unroll
            for (int j = 0; j < 4; j++) c[mi][ni][j] = 0.f;

    packed_mainloop(a_g, b_g, smh, sb, tid, wr, wc, lid, c);

    // epilogue: scatter to out[(tok*128 + d)*16 + e]
#pragma unroll
    for (int mi = 0; mi < 2; mi++) {
        const size_t tok0 = (size_t)tile * M + wr * 32 + mi * 16 + tq;
#pragma unroll
        for (int ni = 0; ni < 8; ni++) {
            const int d0 = wc * 64 + ni * 8 + 2 * tr;
            out[(tok0 * DOUT + d0) * NE + e]           = c[mi][ni][0];
            out[(tok0 * DOUT + d0 + 1) * NE + e]       = c[mi][ni][1];
            out[((tok0 + 8) * DOUT + d0) * NE + e]     = c[mi][ni][2];
            out[((tok0 + 8) * DOUT + d0 + 1) * NE + e] = c[mi][ni][3];
        }
    }
}

// ---------------------------------------------------------------------------
extern "C" void kernel_launch(void* const* d_in, const int* in_sizes, int n_in,
                              void* d_out, int out_size) {
    const float* x  = (const float*)d_in[0];
    const float* w1 = (const float*)d_in[1];
    const float* w2 = (const float*)d_in[2];
    float* out      = (float*)d_out;

    constexpr int NX  = TOK * DIM / 8;
    constexpr int NW1 = NE * DIM * HID / 4;
    constexpr int NW2 = NE * HID * DOUT / 4;
    pack_x_kernel <<<(NX  + 255) / 256, 256>>>(x);
    pack_w1_kernel<<<(NW1 + 255) / 256, 256>>>(w1);
    pack_w2_kernel<<<(NW2 + 255) / 256, 256>>>(w2);

    cudaFuncSetAttribute(gemm1_gelu_kernel,
                         cudaFuncAttributeMaxDynamicSharedMemorySize, G_BYTES);
    cudaFuncSetAttribute(gemm2_kernel,
                         cudaFuncAttributeMaxDynamicSharedMemorySize, G_BYTES);

    gemm1_gelu_kernel<<<dim3(NE * (HID / 128), TOK / M), 256, G_BYTES>>>();
    gemm2_kernel<<<dim3(NE, TOK / M), 256, G_BYTES>>>(out);
}